// round 15
// baseline (speedup 1.0000x reference)
#include <cuda_runtime.h>
#include <cuda_bf16.h>
#include <float.h>
#include <math.h>

// Problem constants
#define BB 8
#define LL 200
#define DD 256
#define HH 8
#define HS 32
#define HB 64          // H*B
#define KTOP 20
#define NROW 1600      // B*L
#define LNELEM 409600  // B*L*D
#define PADL 216       // compacted list capacity (>=200, mult of 8)

// ---------------- device scratch (no allocs allowed) ----------------
__device__ float g_part[2][3][NROW * DD];   // K-split partials
__device__ float g_a[NROW * DD];
__device__ float g_b[NROW * DD];
__device__ float g_w[NROW * DD];
__device__ float g_raw[(size_t)HB * LL * LL];
__device__ unsigned int g_selbits[(size_t)HB * LL * 8]; // topk bitmask, 8 words/row
__device__ unsigned char g_mask[LL * LL];

// ---------------- 3 GEMMs, K-split 2x + mask convert + selbits zero ------
// gridDim = (4, 25, 7). z<6: GEMM partial (matrix z>>1, k-half z&1) with
// 64x64 tile, 4x4/thread, k-chunk 32, double-buffered smem (4 chunks).
// z==6: 100 blocks; block 0 converts the attention mask, rest zero selbits.
__global__ void gemm3mz_kernel(const float* __restrict__ X,
                               const float* __restrict__ W0,
                               const float* __restrict__ W1,
                               const float* __restrict__ W2,
                               const void* __restrict__ msrc) {
    if (blockIdx.z == 6) {
        int bi = blockIdx.y * 4 + blockIdx.x;   // 0..99
        int t = threadIdx.x;
        if (bi == 0) {
            __shared__ int flags[4];
            if (t < 4) flags[t] = 0;
            __syncthreads();
            const unsigned char* p = (const unsigned char*)msrc;
            for (int i = t; i < LL * LL; i += 256) {
                if (p[i]) flags[i & 3] = 1;
            }
            __syncthreads();
            int dt;  // 0=u8, 1=i32, 2=f32
            if (flags[1]) dt = 0;
            else if (flags[2] | flags[3]) dt = 2;
            else dt = 1;
            for (int i = t; i < LL * LL; i += 256) {
                unsigned char m;
                if (dt == 0)      m = (p[i] != 0);
                else if (dt == 1) m = (((const int*)msrc)[i] != 0);
                else              m = (((const float*)msrc)[i] != 0.0f);
                g_mask[i] = m;
            }
        } else {
            for (int i = (bi - 1) * 256 + t; i < HB * LL * 8; i += 99 * 256)
                g_selbits[i] = 0u;
        }
        return;
    }

    int mat = blockIdx.z >> 1;
    int kh  = blockIdx.z & 1;           // k half: 0 -> [0,128), 1 -> [128,256)
    const float* W = (mat == 0) ? W0 : (mat == 1) ? W1 : W2;
    float* O = g_part[kh][mat];

    __shared__ float As[2][32][68];   // [buf][k][m-row]
    __shared__ float Bs[2][32][68];   // [buf][k][n-row]
    int i0 = blockIdx.y * 64;
    int o0 = blockIdx.x * 64;
    int t = threadIdx.x;
    int tx = t & 15, ty = t >> 4;

    // loader mapping: thread t -> row lr (0..63), 8 consecutive k at lkb
    int lr = t >> 2;
    int lkb = (t & 3) * 8;
    int kbase = kh * 128;

    const float* xsrc = &X[(size_t)(i0 + lr) * DD + kbase + lkb];
    const float* wsrc = &W[(size_t)(o0 + lr) * DD + kbase + lkb];

    float4 xa0 = *(const float4*)(xsrc + 0);
    float4 xa1 = *(const float4*)(xsrc + 4);
    float4 wa0 = *(const float4*)(wsrc + 0);
    float4 wa1 = *(const float4*)(wsrc + 4);

    float acc[4][4];
#pragma unroll
    for (int i = 0; i < 4; i++)
#pragma unroll
        for (int j = 0; j < 4; j++) acc[i][j] = 0.f;

    int buf = 0;
    for (int k0 = 0; k0 < 128; k0 += 32) {
        As[buf][lkb + 0][lr] = xa0.x; As[buf][lkb + 1][lr] = xa0.y;
        As[buf][lkb + 2][lr] = xa0.z; As[buf][lkb + 3][lr] = xa0.w;
        As[buf][lkb + 4][lr] = xa1.x; As[buf][lkb + 5][lr] = xa1.y;
        As[buf][lkb + 6][lr] = xa1.z; As[buf][lkb + 7][lr] = xa1.w;
        Bs[buf][lkb + 0][lr] = wa0.x; Bs[buf][lkb + 1][lr] = wa0.y;
        Bs[buf][lkb + 2][lr] = wa0.z; Bs[buf][lkb + 3][lr] = wa0.w;
        Bs[buf][lkb + 4][lr] = wa1.x; Bs[buf][lkb + 5][lr] = wa1.y;
        Bs[buf][lkb + 6][lr] = wa1.z; Bs[buf][lkb + 7][lr] = wa1.w;
        __syncthreads();
        if (k0 + 32 < 128) {
            xa0 = *(const float4*)(xsrc + k0 + 32);
            xa1 = *(const float4*)(xsrc + k0 + 36);
            wa0 = *(const float4*)(wsrc + k0 + 32);
            wa1 = *(const float4*)(wsrc + k0 + 36);
        }
#pragma unroll
        for (int kk = 0; kk < 32; kk++) {
            float4 a4 = *(const float4*)&As[buf][kk][ty * 4];
            float4 b4 = *(const float4*)&Bs[buf][kk][tx * 4];
            float am[4] = {a4.x, a4.y, a4.z, a4.w};
            float bn[4] = {b4.x, b4.y, b4.z, b4.w};
#pragma unroll
            for (int mi = 0; mi < 4; mi++)
#pragma unroll
                for (int ni = 0; ni < 4; ni++) acc[mi][ni] += am[mi] * bn[ni];
        }
        buf ^= 1;
    }
#pragma unroll
    for (int mi = 0; mi < 4; mi++) {
#pragma unroll
        for (int ni = 0; ni < 4; ni++) {
            O[(size_t)(i0 + ty * 4 + mi) * DD + o0 + tx * 4 + ni] = acc[mi][ni];
        }
    }
}

// ---------------- combine: sum K-halves + bias -> g_a/g_b/g_w ------------
// 300 blocks x 256 threads, 4 float4 per thread per matrix stripe.
__global__ void combine_kernel(const float* __restrict__ B0,
                               const float* __restrict__ B1,
                               const float* __restrict__ B2) {
    int idx = blockIdx.x * 256 + threadIdx.x;          // float4 index
    int total4 = NROW * DD / 4;                        // 102400 per matrix
#pragma unroll
    for (int mat = 0; mat < 3; mat++) {
        const float* Bv = (mat == 0) ? B0 : (mat == 1) ? B1 : B2;
        float* O = (mat == 0) ? g_a : (mat == 1) ? g_b : g_w;
        for (int i = idx; i < total4; i += 300 * 256) {
            float4 p0 = ((const float4*)g_part[0][mat])[i];
            float4 p1 = ((const float4*)g_part[1][mat])[i];
            float4 bv = *(const float4*)&Bv[(i * 4) & (DD - 1)];
            float4 r;
            r.x = p0.x + p1.x + bv.x;
            r.y = p0.y + p1.y + bv.y;
            r.z = p0.z + p1.z + bv.z;
            r.w = p0.w + p1.w + bv.w;
            ((float4*)O)[i] = r;
        }
    }
}

// ---------------- Pass 1: 4-lanes-per-k geometry + fused top-K -----------
__global__ void raw_kernel(const float* __restrict__ tm) {
    int q = blockIdx.x, b = blockIdx.y;
    int t = threadIdx.x, h = t >> 5, lane = t & 31;
    int ksub = lane >> 2, j4 = lane & 3;
    __shared__ float s_row[8][LL];

    const float* arow = g_a + (size_t)(b * LL + q) * DD + h * HS + j4 * 8;
    float4 af0 = *(const float4*)(arow + 0);
    float4 af1 = *(const float4*)(arow + 4);
    float s = af0.x*af0.x + af0.y*af0.y + af0.z*af0.z + af0.w*af0.w
            + af1.x*af1.x + af1.y*af1.y + af1.z*af1.z + af1.w*af1.w;
    s += __shfl_xor_sync(0xffffffffu, s, 1);
    s += __shfl_xor_sync(0xffffffffu, s, 2);
    float a2 = sqrtf(s);

    const float* tibase = tm + (size_t)(b * LL + q) * LL * DD + h * HS + j4 * 8;
    const float* bbase  = g_b + (size_t)b * LL * DD + h * HS + j4 * 8;
    int hb = h * BB + b;
    size_t rowbase = (size_t)(hb * LL + q) * LL;
    const unsigned char* mrow = g_mask + q * LL;

    for (int kb = 0; kb < LL; kb += 8) {
        int k = kb + ksub;
        float4 tv0 = *(const float4*)(tibase + (size_t)k * DD + 0);
        float4 tv1 = *(const float4*)(tibase + (size_t)k * DD + 4);
        float4 bv0 = *(const float4*)(bbase + (size_t)k * DD + 0);
        float4 bv1 = *(const float4*)(bbase + (size_t)k * DD + 4);
        float c0 = bv0.x + tv0.x, c1 = bv0.y + tv0.y;
        float c2 = bv0.z + tv0.z, c3 = bv0.w + tv0.w;
        float c4 = bv1.x + tv1.x, c5 = bv1.y + tv1.y;
        float c6 = bv1.z + tv1.z, c7 = bv1.w + tv1.w;
        float s1 = af0.x*c0 + af0.y*c1 + af0.z*c2 + af0.w*c3
                 + af1.x*c4 + af1.y*c5 + af1.z*c6 + af1.w*c7;
        float s2 = c0*c0 + c1*c1 + c2*c2 + c3*c3
                 + c4*c4 + c5*c5 + c6*c6 + c7*c7;
        s1 += __shfl_xor_sync(0xffffffffu, s1, 1);
        s2 += __shfl_xor_sync(0xffffffffu, s2, 1);
        s1 += __shfl_xor_sync(0xffffffffu, s1, 2);
        s2 += __shfl_xor_sync(0xffffffffu, s2, 2);
        if (j4 == 0) {
            float raw = s1 / (a2 * sqrtf(s2) + 1e-6f);
            if (mrow[k]) raw = 0.f;
            s_row[h][k] = raw;
        }
    }
    __syncwarp();

    for (int i = lane; i < LL; i += 32) g_raw[rowbase + i] = s_row[h][i];

    // ---- fused top-K (jax.lax.top_k tie semantics: ties -> lower index) ----
    float v[7];
#pragma unroll
    for (int i = 0; i < 7; i++) {
        int g = lane + i * 32;
        v[i] = (g < LL) ? s_row[h][g] : -FLT_MAX;
    }
    size_t bits_row = (size_t)(hb * LL + q) * 8;
    for (int it = 0; it < KTOP; it++) {
        float bv = -FLT_MAX;
        int bi = 1 << 30;
#pragma unroll
        for (int i = 0; i < 7; i++) {
            if (v[i] > bv) { bv = v[i]; bi = lane + i * 32; }
        }
#pragma unroll
        for (int off = 16; off; off >>= 1) {
            float ov = __shfl_xor_sync(0xffffffffu, bv, off);
            int   oi = __shfl_xor_sync(0xffffffffu, bi, off);
            if (ov > bv || (ov == bv && oi < bi)) { bv = ov; bi = oi; }
        }
        if (lane == (bi & 31)) v[bi >> 5] = -FLT_MAX;
        if (lane == 0) {
            atomicOr(&g_selbits[bits_row + (bi >> 5)], 1u << (bi & 31));
            atomicOr(&g_selbits[(size_t)(hb * LL + bi) * 8 + (q >> 5)], 1u << (q & 31));
        }
    }
}

// ---------------- Pass 2: compacted + padded gather, LayerNorm -----------
__global__ void out_kernel(const float* __restrict__ tm,
                           const float* __restrict__ gamma,
                           const float* __restrict__ beta,
                           float* __restrict__ out, int out_size) {
    int q = blockIdx.x, b = blockIdx.y;
    int t = threadIdx.x, h = t >> 5, lane = t & 31;
    int hb = h * BB + b;
    __shared__ short s_idx[8][PADL];
    __shared__ float s_val[8][PADL];
    __shared__ float rs[8];

    size_t base = (size_t)(hb * LL + q) * LL;
    size_t bits_row = (size_t)(hb * LL + q) * 8;
    int cnt = 0;
#pragma unroll
    for (int c = 0; c < 7; c++) {
        unsigned m = g_selbits[bits_row + c];    // broadcast load
        int i = c * 32 + lane;
        if ((m >> lane) & 1u) {
            int pos = cnt + __popc(m & ((1u << lane) - 1u));
            s_idx[h][pos] = (short)i;
            s_val[h][pos] = g_raw[base + i];
        }
        cnt += __popc(m);
    }
    __syncwarp();
    int cnt_pad = (cnt + 15) & ~15;
    for (int i = cnt + lane; i < cnt_pad; i += 32) {
        s_idx[h][i] = s_idx[h][0];
        s_val[h][i] = 0.f;
    }
    __syncwarp();

    const float* tirow = tm + (size_t)(b * LL + q) * LL * DD + t;
    const float* wcol  = g_w + (size_t)b * LL * DD + t;
    float acc_o = 0.f, acc_t = 0.f;
    for (int p = 0; p < cnt_pad; p += 16) {
#pragma unroll
        for (int u = 0; u < 16; u++) {
            int k = s_idx[h][p + u];
            float r = s_val[h][p + u];
            acc_o += r * wcol[(size_t)k * DD];
            acc_t += r * tirow[(size_t)k * DD];
        }
    }

    // LayerNorm over the 256 outputs of this block
    float sum = acc_o;
#pragma unroll
    for (int off = 16; off; off >>= 1) sum += __shfl_xor_sync(0xffffffffu, sum, off);
    if (lane == 0) rs[h] = sum;
    __syncthreads();
    float tot = 0.f;
#pragma unroll
    for (int i = 0; i < 8; i++) tot += rs[i];
    float mu = tot * (1.f / 256.f);
    __syncthreads();

    float d = acc_o - mu;
    float sq = d * d;
#pragma unroll
    for (int off = 16; off; off >>= 1) sq += __shfl_xor_sync(0xffffffffu, sq, off);
    if (lane == 0) rs[h] = sq;
    __syncthreads();
    float totq = 0.f;
#pragma unroll
    for (int i = 0; i < 8; i++) totq += rs[i];
    float var = totq * (1.f / 256.f);

    float ln = d * rsqrtf(var + 1e-8f) * gamma[t] + beta[t];
    size_t o = (size_t)(b * LL + q) * DD + t;
    out[o] = ln;
    if (out_size > LNELEM) out[LNELEM + o] = acc_t;
}

// ---------------- launch ----------------
extern "C" void kernel_launch(void* const* d_in, const int* in_sizes, int n_in,
                              void* d_out, int out_size) {
    const float* seqs    = (const float*)d_in[0];
    const void*  amask   = d_in[1];
    const float* tm      = (const float*)d_in[2];
    const float* conv1_w = (const float*)d_in[3];
    const float* conv1_b = (const float*)d_in[4];
    const float* conv2_w = (const float*)d_in[5];
    const float* conv2_b = (const float*)d_in[6];
    const float* W_w     = (const float*)d_in[7];
    const float* W_b     = (const float*)d_in[8];
    const float* ln_g    = (const float*)d_in[9];
    const float* ln_b    = (const float*)d_in[10];
    float* out = (float*)d_out;

    gemm3mz_kernel<<<dim3(4, 25, 7), 256>>>(seqs, conv1_w, conv2_w, W_w, amask);
    combine_kernel<<<300, 256>>>(conv1_b, conv2_b, W_b);
    raw_kernel<<<dim3(LL, BB), 256>>>(tm);
    out_kernel<<<dim3(LL, BB), 256>>>(tm, ln_g, ln_b, out, out_size);
}

// round 16
// speedup vs baseline: 1.2386x; 1.2386x over previous
#include <cuda_runtime.h>
#include <cuda_bf16.h>
#include <float.h>
#include <math.h>

// Problem constants
#define BB 8
#define LL 200
#define DD 256
#define HH 8
#define HS 32
#define HB 64          // H*B
#define KTOP 20
#define NROW 1600      // B*L
#define LNELEM 409600  // B*L*D
#define PADL 216       // compacted list capacity (>=200, mult of 8)

// ---------------- device scratch (no allocs allowed) ----------------
__device__ float g_a[NROW * DD];
__device__ float g_b[NROW * DD];
__device__ float g_w[NROW * DD];
__device__ float g_raw[(size_t)HB * LL * LL];
__device__ unsigned int g_selbits[(size_t)HB * LL * 8]; // topk bitmask, 8 words/row
__device__ unsigned char g_mask[LL * LL];

// ---------------- 3 fused GEMMs + mask convert + selbits zero ------------
// gridDim = (2, 25, 4), 512 threads. z<3: GEMM out = X @ W.T + bias with a
// 64x128 tile, 4x4 per thread, k-chunk 32 -> 150 GEMM blocks = ONE wave on
// 148 SMs (vs 2.7 waves before; the kernel is wave-quantized).
// z==3: 50 blocks; block 0 converts the attention mask, rest zero selbits.
__global__ void gemm3mz_kernel(const float* __restrict__ X,
                               const float* __restrict__ W0, const float* __restrict__ B0,
                               const float* __restrict__ W1, const float* __restrict__ B1,
                               const float* __restrict__ W2, const float* __restrict__ B2,
                               const void* __restrict__ msrc) {
    if (blockIdx.z == 3) {
        int bi = blockIdx.y * 2 + blockIdx.x;   // 0..49
        int t = threadIdx.x;
        if (bi == 0) {
            __shared__ int flags[4];
            if (t < 4) flags[t] = 0;
            __syncthreads();
            const unsigned char* p = (const unsigned char*)msrc;
            for (int i = t; i < LL * LL; i += 512) {
                if (p[i]) flags[i & 3] = 1;
            }
            __syncthreads();
            int dt;  // 0=u8, 1=i32, 2=f32
            if (flags[1]) dt = 0;
            else if (flags[2] | flags[3]) dt = 2;
            else dt = 1;
            for (int i = t; i < LL * LL; i += 512) {
                unsigned char m;
                if (dt == 0)      m = (p[i] != 0);
                else if (dt == 1) m = (((const int*)msrc)[i] != 0);
                else              m = (((const float*)msrc)[i] != 0.0f);
                g_mask[i] = m;
            }
        } else {
            for (int i = (bi - 1) * 512 + t; i < HB * LL * 8; i += 49 * 512)
                g_selbits[i] = 0u;
        }
        return;
    }

    const float* W; const float* Bv; float* O;
    if (blockIdx.z == 0)      { W = W0; Bv = B0; O = g_a; }
    else if (blockIdx.z == 1) { W = W1; Bv = B1; O = g_b; }
    else                      { W = W2; Bv = B2; O = g_w; }

    __shared__ float As[32][68];    // [k][m-row], 64 rows
    __shared__ float Bs[32][132];   // [k][n-row], 128 rows
    int i0 = blockIdx.y * 64;       // M tile (25)
    int o0 = blockIdx.x * 128;      // N tile (2)
    int t = threadIdx.x;
    int tx = t & 31, ty = t >> 5;   // 32 col-groups x 16 row-groups

    // loader mappings
    int lr  = t >> 3;               // 0..63  : X row
    int lkb = (t & 7) * 4;          // one float4 of k
    int wr  = t >> 2;               // 0..127 : W row
    int wkb = (t & 3) * 8;          // two float4 of k

    const float* xsrc = &X[(size_t)(i0 + lr) * DD + lkb];
    const float* wsrc = &W[(size_t)(o0 + wr) * DD + wkb];

    float4 xa  = *(const float4*)xsrc;
    float4 wa0 = *(const float4*)(wsrc + 0);
    float4 wa1 = *(const float4*)(wsrc + 4);

    float acc[4][4];
#pragma unroll
    for (int i = 0; i < 4; i++)
#pragma unroll
        for (int j = 0; j < 4; j++) acc[i][j] = 0.f;

    for (int k0 = 0; k0 < DD; k0 += 32) {
        As[lkb + 0][lr] = xa.x; As[lkb + 1][lr] = xa.y;
        As[lkb + 2][lr] = xa.z; As[lkb + 3][lr] = xa.w;
        Bs[wkb + 0][wr] = wa0.x; Bs[wkb + 1][wr] = wa0.y;
        Bs[wkb + 2][wr] = wa0.z; Bs[wkb + 3][wr] = wa0.w;
        Bs[wkb + 4][wr] = wa1.x; Bs[wkb + 5][wr] = wa1.y;
        Bs[wkb + 6][wr] = wa1.z; Bs[wkb + 7][wr] = wa1.w;
        __syncthreads();
        if (k0 + 32 < DD) {   // prefetch next chunk while computing this one
            xa  = *(const float4*)(xsrc + k0 + 32);
            wa0 = *(const float4*)(wsrc + k0 + 32);
            wa1 = *(const float4*)(wsrc + k0 + 36);
        }
#pragma unroll
        for (int kk = 0; kk < 32; kk++) {
            float4 a4 = *(const float4*)&As[kk][ty * 4];   // warp-broadcast
            float4 b4 = *(const float4*)&Bs[kk][tx * 4];
            float am[4] = {a4.x, a4.y, a4.z, a4.w};
            float bn[4] = {b4.x, b4.y, b4.z, b4.w};
#pragma unroll
            for (int mi = 0; mi < 4; mi++)
#pragma unroll
                for (int ni = 0; ni < 4; ni++) acc[mi][ni] += am[mi] * bn[ni];
        }
        __syncthreads();
    }
#pragma unroll
    for (int mi = 0; mi < 4; mi++) {
#pragma unroll
        for (int ni = 0; ni < 4; ni++) {
            int oo = o0 + tx * 4 + ni;
            O[(size_t)(i0 + ty * 4 + mi) * DD + oo] = acc[mi][ni] + Bv[oo];
        }
    }
}

// ---------------- Pass 1: 4-lanes-per-k geometry + fused top-K -----------
// Block = (q, b), warp h = head h. ksub = lane/4 covers 8 k per iteration;
// j4 = lane%4 owns 8 floats of the head dim. 4 SHFL per 8 k.
__global__ void raw_kernel(const float* __restrict__ tm) {
    int q = blockIdx.x, b = blockIdx.y;
    int t = threadIdx.x, h = t >> 5, lane = t & 31;
    int ksub = lane >> 2, j4 = lane & 3;
    __shared__ float s_row[8][LL];

    const float* arow = g_a + (size_t)(b * LL + q) * DD + h * HS + j4 * 8;
    float4 af0 = *(const float4*)(arow + 0);
    float4 af1 = *(const float4*)(arow + 4);
    float s = af0.x*af0.x + af0.y*af0.y + af0.z*af0.z + af0.w*af0.w
            + af1.x*af1.x + af1.y*af1.y + af1.z*af1.z + af1.w*af1.w;
    s += __shfl_xor_sync(0xffffffffu, s, 1);
    s += __shfl_xor_sync(0xffffffffu, s, 2);
    float a2 = sqrtf(s);

    const float* tibase = tm + (size_t)(b * LL + q) * LL * DD + h * HS + j4 * 8;
    const float* bbase  = g_b + (size_t)b * LL * DD + h * HS + j4 * 8;
    int hb = h * BB + b;
    size_t rowbase = (size_t)(hb * LL + q) * LL;
    const unsigned char* mrow = g_mask + q * LL;

    for (int kb = 0; kb < LL; kb += 8) {
        int k = kb + ksub;
        float4 tv0 = *(const float4*)(tibase + (size_t)k * DD + 0);
        float4 tv1 = *(const float4*)(tibase + (size_t)k * DD + 4);
        float4 bv0 = *(const float4*)(bbase + (size_t)k * DD + 0);
        float4 bv1 = *(const float4*)(bbase + (size_t)k * DD + 4);
        float c0 = bv0.x + tv0.x, c1 = bv0.y + tv0.y;
        float c2 = bv0.z + tv0.z, c3 = bv0.w + tv0.w;
        float c4 = bv1.x + tv1.x, c5 = bv1.y + tv1.y;
        float c6 = bv1.z + tv1.z, c7 = bv1.w + tv1.w;
        float s1 = af0.x*c0 + af0.y*c1 + af0.z*c2 + af0.w*c3
                 + af1.x*c4 + af1.y*c5 + af1.z*c6 + af1.w*c7;
        float s2 = c0*c0 + c1*c1 + c2*c2 + c3*c3
                 + c4*c4 + c5*c5 + c6*c6 + c7*c7;
        s1 += __shfl_xor_sync(0xffffffffu, s1, 1);
        s2 += __shfl_xor_sync(0xffffffffu, s2, 1);
        s1 += __shfl_xor_sync(0xffffffffu, s1, 2);
        s2 += __shfl_xor_sync(0xffffffffu, s2, 2);
        if (j4 == 0) {
            float raw = s1 / (a2 * sqrtf(s2) + 1e-6f);
            if (mrow[k]) raw = 0.f;
            s_row[h][k] = raw;
        }
    }
    __syncwarp();

    for (int i = lane; i < LL; i += 32) g_raw[rowbase + i] = s_row[h][i];

    // ---- fused top-K (jax.lax.top_k tie semantics: ties -> lower index) ----
    float v[7];
#pragma unroll
    for (int i = 0; i < 7; i++) {
        int g = lane + i * 32;
        v[i] = (g < LL) ? s_row[h][g] : -FLT_MAX;
    }
    size_t bits_row = (size_t)(hb * LL + q) * 8;
    for (int it = 0; it < KTOP; it++) {
        float bv = -FLT_MAX;
        int bi = 1 << 30;
#pragma unroll
        for (int i = 0; i < 7; i++) {
            if (v[i] > bv) { bv = v[i]; bi = lane + i * 32; }
        }
#pragma unroll
        for (int off = 16; off; off >>= 1) {
            float ov = __shfl_xor_sync(0xffffffffu, bv, off);
            int   oi = __shfl_xor_sync(0xffffffffu, bi, off);
            if (ov > bv || (ov == bv && oi < bi)) { bv = ov; bi = oi; }
        }
        if (lane == (bi & 31)) v[bi >> 5] = -FLT_MAX;
        if (lane == 0) {
            atomicOr(&g_selbits[bits_row + (bi >> 5)], 1u << (bi & 31));
            atomicOr(&g_selbits[(size_t)(hb * LL + bi) * 8 + (q >> 5)], 1u << (q & 31));
        }
    }
}

// ---------------- Pass 2: compacted + padded gather, LayerNorm -----------
__global__ void out_kernel(const float* __restrict__ tm,
                           const float* __restrict__ gamma,
                           const float* __restrict__ beta,
                           float* __restrict__ out, int out_size) {
    int q = blockIdx.x, b = blockIdx.y;
    int t = threadIdx.x, h = t >> 5, lane = t & 31;
    int hb = h * BB + b;
    __shared__ short s_idx[8][PADL];
    __shared__ float s_val[8][PADL];
    __shared__ float rs[8];

    size_t base = (size_t)(hb * LL + q) * LL;
    size_t bits_row = (size_t)(hb * LL + q) * 8;
    int cnt = 0;
#pragma unroll
    for (int c = 0; c < 7; c++) {
        unsigned m = g_selbits[bits_row + c];    // broadcast load
        int i = c * 32 + lane;
        if ((m >> lane) & 1u) {
            int pos = cnt + __popc(m & ((1u << lane) - 1u));
            s_idx[h][pos] = (short)i;
            s_val[h][pos] = g_raw[base + i];
        }
        cnt += __popc(m);
    }
    __syncwarp();
    int cnt_pad = (cnt + 15) & ~15;
    for (int i = cnt + lane; i < cnt_pad; i += 32) {
        s_idx[h][i] = s_idx[h][0];
        s_val[h][i] = 0.f;
    }
    __syncwarp();

    const float* tirow = tm + (size_t)(b * LL + q) * LL * DD + t;
    const float* wcol  = g_w + (size_t)b * LL * DD + t;
    float acc_o = 0.f, acc_t = 0.f;
    for (int p = 0; p < cnt_pad; p += 16) {
#pragma unroll
        for (int u = 0; u < 16; u++) {
            int k = s_idx[h][p + u];
            float r = s_val[h][p + u];
            acc_o += r * wcol[(size_t)k * DD];
            acc_t += r * tirow[(size_t)k * DD];
        }
    }

    // LayerNorm over the 256 outputs of this block
    float sum = acc_o;
#pragma unroll
    for (int off = 16; off; off >>= 1) sum += __shfl_xor_sync(0xffffffffu, sum, off);
    if (lane == 0) rs[h] = sum;
    __syncthreads();
    float tot = 0.f;
#pragma unroll
    for (int i = 0; i < 8; i++) tot += rs[i];
    float mu = tot * (1.f / 256.f);
    __syncthreads();

    float d = acc_o - mu;
    float sq = d * d;
#pragma unroll
    for (int off = 16; off; off >>= 1) sq += __shfl_xor_sync(0xffffffffu, sq, off);
    if (lane == 0) rs[h] = sq;
    __syncthreads();
    float totq = 0.f;
#pragma unroll
    for (int i = 0; i < 8; i++) totq += rs[i];
    float var = totq * (1.f / 256.f);

    float ln = d * rsqrtf(var + 1e-8f) * gamma[t] + beta[t];
    size_t o = (size_t)(b * LL + q) * DD + t;
    out[o] = ln;
    if (out_size > LNELEM) out[LNELEM + o] = acc_t;
}

// ---------------- launch ----------------
extern "C" void kernel_launch(void* const* d_in, const int* in_sizes, int n_in,
                              void* d_out, int out_size) {
    const float* seqs    = (const float*)d_in[0];
    const void*  amask   = d_in[1];
    const float* tm      = (const float*)d_in[2];
    const float* conv1_w = (const float*)d_in[3];
    const float* conv1_b = (const float*)d_in[4];
    const float* conv2_w = (const float*)d_in[5];
    const float* conv2_b = (const float*)d_in[6];
    const float* W_w     = (const float*)d_in[7];
    const float* W_b     = (const float*)d_in[8];
    const float* ln_g    = (const float*)d_in[9];
    const float* ln_b    = (const float*)d_in[10];
    float* out = (float*)d_out;

    gemm3mz_kernel<<<dim3(2, 25, 4), 512>>>(
        seqs, conv1_w, conv1_b, conv2_w, conv2_b, W_w, W_b, amask);
    raw_kernel<<<dim3(LL, BB), 256>>>(tm);
    out_kernel<<<dim3(LL, BB), 256>>>(tm, ln_g, ln_b, out, out_size);
}